// round 5
// baseline (speedup 1.0000x reference)
#include <cuda_runtime.h>
#include <math.h>

// Problem constants
constexpr int FH   = 96;
constexpr int FW   = 96;
constexpr int FC   = 512;
constexpr int FB   = 16;
constexpr int NROI = 32;
constexpr int NREG = 50;          // 1 + 4 + 9 + 36
constexpr int C4   = FC / 4;      // 128 float4 channels
constexpr int ROWSTRIDE = FW * C4;  // float4 units per image row = 12288

// Region table: per (roi, region) -> x1, x2, y1, y2
__device__ int4 d_regions[NROI * NREG];

// ---------------------------------------------------------------------------
// Exact Python-double region boundaries (identical to PASSING R1/R3 kernels).
//   cl = h / p governs x axis (reference quirk), rl = w / p governs y axis.
//   round() = banker's rounding -> rint(); forced RN double ops (no FMA drift).
// ---------------------------------------------------------------------------
__global__ void compute_regions_kernel(const int* __restrict__ rois) {
    int r = blockIdx.x * blockDim.x + threadIdx.x;
    if (r >= NROI * NREG) return;

    int roi = r / NREG;
    int k   = r % NREG;

    int P, off;
    if      (k < 1)  { P = 1; off = 0; }
    else if (k < 5)  { P = 2; off = 1; }
    else if (k < 14) { P = 3; off = 5; }
    else             { P = 6; off = 14; }
    int idx = k - off;
    int ix  = idx / P;
    int jy  = idx % P;

    double x = (double)rois[roi * 4 + 0];
    double y = (double)rois[roi * 4 + 1];
    double w = (double)rois[roi * 4 + 2];
    double h = (double)rois[roi * 4 + 3];

    double cl = h / (double)P;   // x-axis step (reference quirk)
    double rl = w / (double)P;   // y-axis step

    double tx = __dadd_rn(x, __dmul_rn((double)ix, cl));
    int x1 = (int)rint(tx);
    int x2 = (int)rint(__dadd_rn(tx, cl));

    double ty = __dadd_rn(y, __dmul_rn((double)jy, rl));
    int y1 = (int)rint(ty);
    int y2 = (int)rint(__dadd_rn(ty, rl));

    x1 = max(0, min(FW, x1));
    x2 = max(0, min(FW, x2));
    y1 = max(0, min(FH, y1));
    y2 = max(0, min(FH, y2));

    d_regions[r] = make_int4(x1, x2, y1, y2);
}

__device__ __forceinline__ void vmax4(float4& a, const float4 b) {
    a.x = fmaxf(a.x, b.x);
    a.y = fmaxf(a.y, b.y);
    a.z = fmaxf(a.z, b.z);
    a.w = fmaxf(a.w, b.w);
}

// Band order: pool2 j=0,1 -> bands 0,1 (region idx 1+j)
//             pool3 j=0..2 -> bands 2..4 (region idx 5+j)
//             pool6 j=0..5 -> bands 5..10 (region idx 14+j)
constexpr int NBAND = 11;

// ---------------------------------------------------------------------------
// Separable-max kernel. Block = (batch, roi, channel-group of 16 channels).
// Threads: 256 = 64 x-columns x 4 float4-lanes.
// Stage 1: each active thread (x-column xi < h) scans the bbox rows once per
//   containing band (y-chunked by 8 rows so revisits hit L1), producing 11
//   per-band column maxima, each over that band's OWN exact y-range.
// Stage 2: per (region, c4) thread reduces colmax over the region's OWN exact
//   x-range; pool1 = fold of pool2 bands over full x (bit-exact: w/2, h/2
//   exact -> pool2 cuts tile pool1's box exactly). Direct stores, no atomics.
// ---------------------------------------------------------------------------
__global__ void __launch_bounds__(256)
roi_pool_colmax(const float* __restrict__ fm, float* __restrict__ out) {
    __shared__ float4 s_col[NBAND][64][4];      // 45056 B

    int bid = blockIdx.x;
    int cg  = bid & 31;          // channel group (16 channels = 4 float4)
    int roi = (bid >> 5) & 31;
    int b   = bid >> 10;         // batch slowest: co-resident blocks share image

    int tid = threadIdx.x;
    int c4  = tid & 3;           // float4 lane within group
    int xi  = tid >> 2;          // x column 0..63

    const int4* regs = d_regions + roi * NREG;

    // Union bbox = pool1 box exactly: [x, x+h) x [y, y+w)
    int4 r0   = __ldg(&regs[0]);
    int xbase = r0.x, ybase = r0.z;
    int XW    = r0.y - r0.x;     // = h
    int YH    = r0.w - r0.z;     // = w

    // Band y-ranges (relative to ybase), kept in registers (static unroll)
    int by1[NBAND], by2[NBAND];
#pragma unroll
    for (int j = 0; j < 2; j++) { int4 q = __ldg(&regs[1 + j]);  by1[j]     = q.z - ybase; by2[j]     = q.w - ybase; }
#pragma unroll
    for (int j = 0; j < 3; j++) { int4 q = __ldg(&regs[5 + j]);  by1[2 + j] = q.z - ybase; by2[2 + j] = q.w - ybase; }
#pragma unroll
    for (int j = 0; j < 6; j++) { int4 q = __ldg(&regs[14 + j]); by1[5 + j] = q.z - ybase; by2[5 + j] = q.w - ybase; }

    bool active = (xi < XW);

    if (active) {
        const float4* fmp = (const float4*)fm
            + ((size_t)(b * FH + ybase) * FW + (xbase + xi)) * C4 + cg * 4 + c4;

        const float4 NEG = make_float4(-INFINITY, -INFINITY, -INFINITY, -INFINITY);
        float4 acc[NBAND];
#pragma unroll
        for (int bb = 0; bb < NBAND; bb++) acc[bb] = NEG;

        // y-chunks of 8 rows: pool2 streams; pool3/pool6 revisits hit L1
        for (int cc = 0; cc < YH; cc += 8) {
            int ce = min(cc + 8, YH);
#pragma unroll
            for (int bb = 0; bb < NBAND; bb++) {
                int ys = max(by1[bb], cc);
                int ye = min(by2[bb], ce);
                int y = ys;
                for (; y + 2 <= ye; y += 2) {       // unroll-2 for MLP
                    float4 v0 = __ldg(fmp + (size_t)y * ROWSTRIDE);
                    float4 v1 = __ldg(fmp + (size_t)(y + 1) * ROWSTRIDE);
                    vmax4(acc[bb], v0);
                    vmax4(acc[bb], v1);
                }
                if (y < ye)
                    vmax4(acc[bb], __ldg(fmp + (size_t)y * ROWSTRIDE));
            }
        }

#pragma unroll
        for (int bb = 0; bb < NBAND; bb++)
            s_col[bb][xi][c4] = acc[bb];
    }

    __syncthreads();

    // Stage 2: 200 tasks = 50 regions x 4 c4-lanes
    if (tid < 200) {
        int k   = tid >> 2;
        int c4b = tid & 3;

        float4 f = make_float4(-INFINITY, -INFINITY, -INFINITY, -INFINITY);

        if (k == 0) {
            // pool1 = max over pool2 bands {0,1}, full x range (exact fold)
            for (int x = 0; x < XW; x++) {
                vmax4(f, s_col[0][x][c4b]);
                vmax4(f, s_col[1][x][c4b]);
            }
        } else {
            int P, off, bandbase;
            if      (k < 5)  { P = 2; off = 1;  bandbase = 0; }
            else if (k < 14) { P = 3; off = 5;  bandbase = 2; }
            else             { P = 6; off = 14; bandbase = 5; }
            int idx = k - off;
            int i   = idx / P;
            int j   = idx % P;

            int4 rx = __ldg(&regs[off + i * P]);   // x-range depends only on i
            int x1 = rx.x - xbase, x2 = rx.y - xbase;
            int band = bandbase + j;

            for (int x = x1; x < x2; x++)
                vmax4(f, s_col[band][x][c4b]);
        }

        // out float4 layout: [(b*32+roi)*50 + k][128 float4 channels]
        float4* o = (float4*)out
            + (((size_t)(b * NROI + roi) * NREG + k) << 7) + cg * 4 + c4b;
        *o = f;
    }
}

extern "C" void kernel_launch(void* const* d_in, const int* in_sizes, int n_in,
                              void* d_out, int out_size) {
    const float* fm   = (const float*)d_in[0];
    const int*   rois = (const int*)d_in[1];
    float*       out  = (float*)d_out;

    compute_regions_kernel<<<(NROI * NREG + 255) / 256, 256>>>(rois);
    roi_pool_colmax<<<FB * NROI * 32, 256>>>(fm, out);
}

// round 6
// speedup vs baseline: 2.5133x; 2.5133x over previous
#include <cuda_runtime.h>
#include <math.h>

// Problem constants
constexpr int FH   = 96;
constexpr int FW   = 96;
constexpr int FC   = 512;
constexpr int FB   = 16;
constexpr int NROI = 32;
constexpr int NREG = 50;          // 1 + 4 + 9 + 36
constexpr int C4   = FC / 4;      // 128 float4 channels

constexpr int CH   = 8;           // rows per y-chunk
constexpr int NCK  = FH / CH;     // 12 chunks cover all absolute rows

// Region table: per (roi, region) -> x1, x2, y1, y2
__device__ int4 d_regions[NROI * NREG];

// ---------------------------------------------------------------------------
// Exact Python-double region boundaries (identical to PASSING R1/R4 kernels).
// ---------------------------------------------------------------------------
__global__ void compute_regions_kernel(const int* __restrict__ rois) {
    int r = blockIdx.x * blockDim.x + threadIdx.x;
    if (r >= NROI * NREG) return;

    int roi = r / NREG;
    int k   = r % NREG;

    int P, off;
    if      (k < 1)  { P = 1; off = 0; }
    else if (k < 5)  { P = 2; off = 1; }
    else if (k < 14) { P = 3; off = 5; }
    else             { P = 6; off = 14; }
    int idx = k - off;
    int ix  = idx / P;
    int jy  = idx % P;

    double x = (double)rois[roi * 4 + 0];
    double y = (double)rois[roi * 4 + 1];
    double w = (double)rois[roi * 4 + 2];
    double h = (double)rois[roi * 4 + 3];

    double cl = h / (double)P;   // x-axis step (reference quirk)
    double rl = w / (double)P;   // y-axis step

    double tx = __dadd_rn(x, __dmul_rn((double)ix, cl));
    int x1 = (int)rint(tx);
    int x2 = (int)rint(__dadd_rn(tx, cl));

    double ty = __dadd_rn(y, __dmul_rn((double)jy, rl));
    int y1 = (int)rint(ty);
    int y2 = (int)rint(__dadd_rn(ty, rl));

    x1 = max(0, min(FW, x1));
    x2 = max(0, min(FW, x2));
    y1 = max(0, min(FH, y1));
    y2 = max(0, min(FH, y2));

    d_regions[r] = make_int4(x1, x2, y1, y2);
}

// Sign-split float atomic max on raw bits. Invariant "stored = max so far"
// holds under any interleaving:
//   v>=0 via atomicMax(int):  any negative stored value has negative int bits.
//   v<0  via atomicMin(uint): negatives reverse-order as uint (min = float max);
//                             any positive stored value has smaller uint bits.
__device__ __forceinline__ void atomicMaxFloat(float* addr, float v) {
    if (v >= 0.0f) atomicMax((int*)addr, __float_as_int(v));
    else           atomicMin((unsigned int*)addr, __float_as_uint(v));
}

__global__ void init_out_kernel(unsigned int* __restrict__ out, int n4) {
    int i = blockIdx.x * blockDim.x + threadIdx.x;
    if (i < n4) {
        // raw bits of -INFINITY
        ((uint4*)out)[i] = make_uint4(0xFF800000u, 0xFF800000u, 0xFF800000u, 0xFF800000u);
    }
}

__device__ __forceinline__ void vmax4(float4& a, const float4 b) {
    a.x = fmaxf(a.x, b.x);
    a.y = fmaxf(a.y, b.y);
    a.z = fmaxf(a.z, b.z);
    a.w = fmaxf(a.w, b.w);
}

// ---------------------------------------------------------------------------
// Main kernel: one block = (batch, y-chunk, roi, pool in {2,3,6}).
// Each region uses its OWN exact box intersected with the chunk rows; partial
// maxima merged by sign-split atomics. Coalesced: thread = float4 channel.
// ---------------------------------------------------------------------------
__global__ void __launch_bounds__(128)
roi_pool_atomic(const float* __restrict__ fm, float* __restrict__ out) {
    int bid  = blockIdx.x;
    int pool = bid % 3;                      // 0->P2, 1->P3, 2->P6
    int rest = bid / 3;
    int roi  = rest & 31;
    rest >>= 5;
    int ck   = rest % NCK;
    int b    = rest / NCK;

    int P   = (pool == 0) ? 2 : (pool == 1) ? 3 : 6;
    int off = (pool == 0) ? 1 : (pool == 1) ? 5 : 14;

    int yc0 = ck * CH;
    int yc1 = yc0 + CH;
    int c   = threadIdx.x;        // float4-channel 0..127

    const int4*   regs = d_regions + roi * NREG + off;
    const float4* fmb  = (const float4*)fm + (size_t)b * FH * FW * C4 + c;
    float*        outb = out + (((size_t)(b * NROI + roi) * NREG + off) << 9) + c * 4;

    const float4 NEG = make_float4(-INFINITY, -INFINITY, -INFINITY, -INFINITY);

    for (int j = 0; j < P; j++) {
        int4 rj = __ldg(&regs[j]);                 // region (ix=0, jy=j): y-range
        int y1 = max(rj.z, yc0), y2 = min(rj.w, yc1);
        if (y1 >= y2) continue;

        for (int i = 0; i < P; i++) {
            int4 ri = __ldg(&regs[i * P]);         // region (ix=i, jy=0): x-range
            int x1 = ri.x, x2 = ri.y;

            float4 a0 = NEG, a1 = NEG;             // dual acc: halve fmax chain
            for (int y = y1; y < y2; y++) {
                const float4* row = fmb + (size_t)y * FW * C4;
                int x = x1;
                for (; x + 4 <= x2; x += 4) {      // unroll-4 for MLP
                    vmax4(a0, __ldg(row + (size_t)x * C4));
                    vmax4(a1, __ldg(row + (size_t)(x + 1) * C4));
                    vmax4(a0, __ldg(row + (size_t)(x + 2) * C4));
                    vmax4(a1, __ldg(row + (size_t)(x + 3) * C4));
                }
                for (; x < x2; x++)
                    vmax4(a0, __ldg(row + (size_t)x * C4));
            }
            vmax4(a0, a1);

            float* o = outb + ((size_t)(i * P + j) << 9);
            atomicMaxFloat(o + 0, a0.x);
            atomicMaxFloat(o + 1, a0.y);
            atomicMaxFloat(o + 2, a0.z);
            atomicMaxFloat(o + 3, a0.w);
        }
    }
}

// ---------------------------------------------------------------------------
// pool1 = max over pool2's 4 regions (bit-exact fold: h/2, w/2 exact doubles,
// pool2's cuts tile pool1's box exactly; validated rel_err=0 in R5).
// One thread per (batch, roi, float4-channel).
// ---------------------------------------------------------------------------
__global__ void pool1_fold_kernel(float* __restrict__ out) {
    int t = blockIdx.x * blockDim.x + threadIdx.x;
    if (t >= FB * NROI * C4) return;
    int c4  = t & 127;
    int pr  = t >> 7;             // b*32 + roi

    float4* base = (float4*)out + ((size_t)pr * NREG) * C4 + c4;
    float4 f = base[1 * C4];
    vmax4(f, base[2 * C4]);
    vmax4(f, base[3 * C4]);
    vmax4(f, base[4 * C4]);
    base[0] = f;
}

extern "C" void kernel_launch(void* const* d_in, const int* in_sizes, int n_in,
                              void* d_out, int out_size) {
    const float* fm   = (const float*)d_in[0];
    const int*   rois = (const int*)d_in[1];
    float*       out  = (float*)d_out;

    int n4 = out_size / 4;
    int ib = (n4 + 255) / 256;

    init_out_kernel<<<ib, 256>>>((unsigned int*)out, n4);
    compute_regions_kernel<<<(NROI * NREG + 255) / 256, 256>>>(rois);
    roi_pool_atomic<<<FB * NCK * NROI * 3, 128>>>(fm, out);
    pool1_fold_kernel<<<(FB * NROI * C4 + 127) / 128, 128>>>(out);
}

// round 7
// speedup vs baseline: 2.5180x; 1.0018x over previous
#include <cuda_runtime.h>
#include <math.h>

// Problem constants
constexpr int FH   = 96;
constexpr int FW   = 96;
constexpr int FC   = 512;
constexpr int FB   = 16;
constexpr int NROI = 32;
constexpr int NREG = 50;          // 1 + 4 + 9 + 36
constexpr int C4   = FC / 4;      // 128 float4 channels

constexpr int CH   = 8;           // rows per y-chunk
constexpr int NCK  = FH / CH;     // 12 chunks cover all absolute rows

// Region table: per (roi, region) -> x1, x2, y1, y2
__device__ int4 d_regions[NROI * NREG];

// ---------------------------------------------------------------------------
// Exact Python-double region boundaries (identical to PASSING R1/R4 kernels).
// ---------------------------------------------------------------------------
__global__ void compute_regions_kernel(const int* __restrict__ rois) {
    int r = blockIdx.x * blockDim.x + threadIdx.x;
    if (r >= NROI * NREG) return;

    int roi = r / NREG;
    int k   = r % NREG;

    int P, off;
    if      (k < 1)  { P = 1; off = 0; }
    else if (k < 5)  { P = 2; off = 1; }
    else if (k < 14) { P = 3; off = 5; }
    else             { P = 6; off = 14; }
    int idx = k - off;
    int ix  = idx / P;
    int jy  = idx % P;

    double x = (double)rois[roi * 4 + 0];
    double y = (double)rois[roi * 4 + 1];
    double w = (double)rois[roi * 4 + 2];
    double h = (double)rois[roi * 4 + 3];

    double cl = h / (double)P;   // x-axis step (reference quirk)
    double rl = w / (double)P;   // y-axis step

    double tx = __dadd_rn(x, __dmul_rn((double)ix, cl));
    int x1 = (int)rint(tx);
    int x2 = (int)rint(__dadd_rn(tx, cl));

    double ty = __dadd_rn(y, __dmul_rn((double)jy, rl));
    int y1 = (int)rint(ty);
    int y2 = (int)rint(__dadd_rn(ty, rl));

    x1 = max(0, min(FW, x1));
    x2 = max(0, min(FW, x2));
    y1 = max(0, min(FH, y1));
    y2 = max(0, min(FH, y2));

    d_regions[r] = make_int4(x1, x2, y1, y2);
}

// Sign-split float atomic max on raw bits. Invariant "stored = max so far"
// holds under any interleaving:
//   v>=0 via atomicMax(int):  any negative stored value has negative int bits.
//   v<0  via atomicMin(uint): negatives reverse-order as uint (min = float max);
//                             any positive stored value has smaller uint bits.
__device__ __forceinline__ void atomicMaxFloat(float* addr, float v) {
    if (v >= 0.0f) atomicMax((int*)addr, __float_as_int(v));
    else           atomicMin((unsigned int*)addr, __float_as_uint(v));
}

__global__ void init_out_kernel(unsigned int* __restrict__ out, int n4) {
    int i = blockIdx.x * blockDim.x + threadIdx.x;
    if (i < n4) {
        // raw bits of -INFINITY
        ((uint4*)out)[i] = make_uint4(0xFF800000u, 0xFF800000u, 0xFF800000u, 0xFF800000u);
    }
}

__device__ __forceinline__ void vmax4(float4& a, const float4 b) {
    a.x = fmaxf(a.x, b.x);
    a.y = fmaxf(a.y, b.y);
    a.z = fmaxf(a.z, b.z);
    a.w = fmaxf(a.w, b.w);
}

// ---------------------------------------------------------------------------
// Main kernel: one block = (batch, y-chunk, roi, pool in {2,3,6}).
// Each region uses its OWN exact box intersected with the chunk rows; partial
// maxima merged by sign-split atomics. Coalesced: thread = float4 channel.
// ---------------------------------------------------------------------------
__global__ void __launch_bounds__(128)
roi_pool_atomic(const float* __restrict__ fm, float* __restrict__ out) {
    int bid  = blockIdx.x;
    int pool = bid % 3;                      // 0->P2, 1->P3, 2->P6
    int rest = bid / 3;
    int roi  = rest & 31;
    rest >>= 5;
    int ck   = rest % NCK;
    int b    = rest / NCK;

    int P   = (pool == 0) ? 2 : (pool == 1) ? 3 : 6;
    int off = (pool == 0) ? 1 : (pool == 1) ? 5 : 14;

    int yc0 = ck * CH;
    int yc1 = yc0 + CH;
    int c   = threadIdx.x;        // float4-channel 0..127

    const int4*   regs = d_regions + roi * NREG + off;
    const float4* fmb  = (const float4*)fm + (size_t)b * FH * FW * C4 + c;
    float*        outb = out + (((size_t)(b * NROI + roi) * NREG + off) << 9) + c * 4;

    const float4 NEG = make_float4(-INFINITY, -INFINITY, -INFINITY, -INFINITY);

    for (int j = 0; j < P; j++) {
        int4 rj = __ldg(&regs[j]);                 // region (ix=0, jy=j): y-range
        int y1 = max(rj.z, yc0), y2 = min(rj.w, yc1);
        if (y1 >= y2) continue;

        for (int i = 0; i < P; i++) {
            int4 ri = __ldg(&regs[i * P]);         // region (ix=i, jy=0): x-range
            int x1 = ri.x, x2 = ri.y;

            float4 a0 = NEG, a1 = NEG;             // dual acc: halve fmax chain
            for (int y = y1; y < y2; y++) {
                const float4* row = fmb + (size_t)y * FW * C4;
                int x = x1;
                for (; x + 4 <= x2; x += 4) {      // unroll-4 for MLP
                    vmax4(a0, __ldg(row + (size_t)x * C4));
                    vmax4(a1, __ldg(row + (size_t)(x + 1) * C4));
                    vmax4(a0, __ldg(row + (size_t)(x + 2) * C4));
                    vmax4(a1, __ldg(row + (size_t)(x + 3) * C4));
                }
                for (; x < x2; x++)
                    vmax4(a0, __ldg(row + (size_t)x * C4));
            }
            vmax4(a0, a1);

            float* o = outb + ((size_t)(i * P + j) << 9);
            atomicMaxFloat(o + 0, a0.x);
            atomicMaxFloat(o + 1, a0.y);
            atomicMaxFloat(o + 2, a0.z);
            atomicMaxFloat(o + 3, a0.w);
        }
    }
}

// ---------------------------------------------------------------------------
// pool1 = max over pool2's 4 regions (bit-exact fold: h/2, w/2 exact doubles,
// pool2's cuts tile pool1's box exactly; validated rel_err=0 in R5).
// One thread per (batch, roi, float4-channel).
// ---------------------------------------------------------------------------
__global__ void pool1_fold_kernel(float* __restrict__ out) {
    int t = blockIdx.x * blockDim.x + threadIdx.x;
    if (t >= FB * NROI * C4) return;
    int c4  = t & 127;
    int pr  = t >> 7;             // b*32 + roi

    float4* base = (float4*)out + ((size_t)pr * NREG) * C4 + c4;
    float4 f = base[1 * C4];
    vmax4(f, base[2 * C4]);
    vmax4(f, base[3 * C4]);
    vmax4(f, base[4 * C4]);
    base[0] = f;
}

extern "C" void kernel_launch(void* const* d_in, const int* in_sizes, int n_in,
                              void* d_out, int out_size) {
    const float* fm   = (const float*)d_in[0];
    const int*   rois = (const int*)d_in[1];
    float*       out  = (float*)d_out;

    int n4 = out_size / 4;
    int ib = (n4 + 255) / 256;

    init_out_kernel<<<ib, 256>>>((unsigned int*)out, n4);
    compute_regions_kernel<<<(NROI * NREG + 255) / 256, 256>>>(rois);
    roi_pool_atomic<<<FB * NCK * NROI * 3, 128>>>(fm, out);
    pool1_fold_kernel<<<(FB * NROI * C4 + 127) / 128, 128>>>(out);
}

// round 8
// speedup vs baseline: 2.5418x; 1.0095x over previous
#include <cuda_runtime.h>
#include <math.h>

// Problem constants
constexpr int FH   = 96;
constexpr int FW   = 96;
constexpr int FC   = 512;
constexpr int FB   = 16;
constexpr int NROI = 32;
constexpr int NREG = 50;          // 1 + 4 + 9 + 36
constexpr int C4   = FC / 4;      // 128 float4 channels

constexpr int NTASK = 20;         // 6 (P6) + 6 (P3 bands x2) + 8 (P2 bands x4)

// Region table: per (roi, region) -> x1, x2, y1, y2
__device__ int4 d_regions[NROI * NREG];

// ---------------------------------------------------------------------------
// Exact Python-double region boundaries (identical to PASSING R1/R4/R7).
// ---------------------------------------------------------------------------
__global__ void compute_regions_kernel(const int* __restrict__ rois) {
    int r = blockIdx.x * blockDim.x + threadIdx.x;
    if (r >= NROI * NREG) return;

    int roi = r / NREG;
    int k   = r % NREG;

    int P, off;
    if      (k < 1)  { P = 1; off = 0; }
    else if (k < 5)  { P = 2; off = 1; }
    else if (k < 14) { P = 3; off = 5; }
    else             { P = 6; off = 14; }
    int idx = k - off;
    int ix  = idx / P;
    int jy  = idx % P;

    double x = (double)rois[roi * 4 + 0];
    double y = (double)rois[roi * 4 + 1];
    double w = (double)rois[roi * 4 + 2];
    double h = (double)rois[roi * 4 + 3];

    double cl = h / (double)P;   // x-axis step (reference quirk)
    double rl = w / (double)P;   // y-axis step

    double tx = __dadd_rn(x, __dmul_rn((double)ix, cl));
    int x1 = (int)rint(tx);
    int x2 = (int)rint(__dadd_rn(tx, cl));

    double ty = __dadd_rn(y, __dmul_rn((double)jy, rl));
    int y1 = (int)rint(ty);
    int y2 = (int)rint(__dadd_rn(ty, rl));

    x1 = max(0, min(FW, x1));
    x2 = max(0, min(FW, x2));
    y1 = max(0, min(FH, y1));
    y2 = max(0, min(FH, y2));

    d_regions[r] = make_int4(x1, x2, y1, y2);
}

// Sign-split float atomic max on raw bits (proven in R6/R7, rel_err=0).
__device__ __forceinline__ void atomicMaxFloat(float* addr, float v) {
    if (v >= 0.0f) atomicMax((int*)addr, __float_as_int(v));
    else           atomicMin((unsigned int*)addr, __float_as_uint(v));
}

// Init ONLY regions 0..13 (pool1/2/3) per (b, roi): pool6 is direct-stored.
__global__ void init_out14_kernel(unsigned int* __restrict__ out) {
    int i = blockIdx.x * blockDim.x + threadIdx.x;          // uint4 index
    int per = 14 * 128;                                     // uint4 per (b,roi)
    if (i >= FB * NROI * per) return;
    int pr = i / per;
    int k  = i % per;
    ((uint4*)out)[(size_t)pr * NREG * 128 + k] =
        make_uint4(0xFF800000u, 0xFF800000u, 0xFF800000u, 0xFF800000u);
}

__device__ __forceinline__ void vmax4(float4& a, const float4 b) {
    a.x = fmaxf(a.x, b.x);
    a.y = fmaxf(a.y, b.y);
    a.z = fmaxf(a.z, b.z);
    a.w = fmaxf(a.w, b.w);
}

// ---------------------------------------------------------------------------
// Band compute for pool level P at region offset OFF. Processes y in [ys,ye)
// (a sub-range of band j's exact y-range) for all P x-segments, each with its
// OWN exact x-range. DIRECT=true -> plain store (block owns the full region).
// ---------------------------------------------------------------------------
template <int P, int OFF, bool DIRECT>
__device__ __forceinline__ void band_compute(const float4* __restrict__ fmb,
                                             const int4*  __restrict__ regs,
                                             float*       __restrict__ outb,
                                             int j, int ys, int ye) {
    const float4 NEG = make_float4(-INFINITY, -INFINITY, -INFINITY, -INFINITY);
#pragma unroll
    for (int i = 0; i < P; i++) {
        int4 ri = __ldg(&regs[OFF + i * P]);     // x-range depends only on i
        int x1 = ri.x, x2 = ri.y;

        float4 a0 = NEG, a1 = NEG;
        for (int y = ys; y < ye; y++) {
            const float4* row = fmb + (size_t)y * (FW * C4);
            int x = x1;
            for (; x + 4 <= x2; x += 4) {
                vmax4(a0, __ldg(row + (size_t)x * C4));
                vmax4(a1, __ldg(row + (size_t)(x + 1) * C4));
                vmax4(a0, __ldg(row + (size_t)(x + 2) * C4));
                vmax4(a1, __ldg(row + (size_t)(x + 3) * C4));
            }
            for (; x < x2; x++)
                vmax4(a0, __ldg(row + (size_t)x * C4));
        }
        vmax4(a0, a1);

        float* o = outb + ((size_t)(OFF + i * P + j) << 9);
        if (DIRECT) {
            *(float4*)o = a0;
        } else {
            atomicMaxFloat(o + 0, a0.x);
            atomicMaxFloat(o + 1, a0.y);
            atomicMaxFloat(o + 2, a0.z);
            atomicMaxFloat(o + 3, a0.w);
        }
    }
}

// ---------------------------------------------------------------------------
// One block = (batch, roi, task). Tasks are band-aligned:
//   task 0..5   : pool6 band j      -> direct-store its 6 regions (no atomics)
//   task 6..11  : pool3 band j, y-half   -> atomics into 3 regions
//   task 12..19 : pool2 band j, y-quarter-> atomics into 2 regions
// batch slowest -> co-resident blocks share one image in L2.
// ---------------------------------------------------------------------------
__global__ void __launch_bounds__(128)
roi_pool_band(const float* __restrict__ fm, float* __restrict__ out) {
    int bid  = blockIdx.x;
    int task = bid % NTASK;
    int rr   = bid / NTASK;
    int roi  = rr & 31;
    int b    = rr >> 5;
    int c    = threadIdx.x;       // float4-channel 0..127

    const int4*   regs = d_regions + roi * NREG;
    const float4* fmb  = (const float4*)fm + (size_t)b * FH * FW * C4 + c;
    float*        outb = out + (((size_t)(b * NROI + roi) * NREG) << 9) + c * 4;

    if (task < 6) {
        int j = task;
        int4 rj = __ldg(&regs[14 + j]);           // band j exact y-range
        band_compute<6, 14, true>(fmb, regs, outb, j, rj.z, rj.w);
    } else if (task < 12) {
        int t = task - 6;
        int j = t >> 1, hf = t & 1;
        int4 rj = __ldg(&regs[5 + j]);
        int hgt = rj.w - rj.z;
        int ys = rj.z + (hgt * hf)     / 2;
        int ye = rj.z + (hgt * (hf+1)) / 2;
        band_compute<3, 5, false>(fmb, regs, outb, j, ys, ye);
    } else {
        int t = task - 12;
        int j = t >> 2, q = t & 3;
        int4 rj = __ldg(&regs[1 + j]);
        int hgt = rj.w - rj.z;
        int ys = rj.z + (hgt * q)     / 4;
        int ye = rj.z + (hgt * (q+1)) / 4;
        band_compute<2, 1, false>(fmb, regs, outb, j, ys, ye);
    }
}

// pool1 = max over pool2's 4 regions (bit-exact fold; validated rel_err=0).
__global__ void pool1_fold_kernel(float* __restrict__ out) {
    int t = blockIdx.x * blockDim.x + threadIdx.x;
    if (t >= FB * NROI * C4) return;
    int c4 = t & 127;
    int pr = t >> 7;              // b*32 + roi

    float4* base = (float4*)out + ((size_t)pr * NREG) * C4 + c4;
    float4 f = base[1 * C4];
    vmax4(f, base[2 * C4]);
    vmax4(f, base[3 * C4]);
    vmax4(f, base[4 * C4]);
    base[0] = f;
}

extern "C" void kernel_launch(void* const* d_in, const int* in_sizes, int n_in,
                              void* d_out, int out_size) {
    const float* fm   = (const float*)d_in[0];
    const int*   rois = (const int*)d_in[1];
    float*       out  = (float*)d_out;

    compute_regions_kernel<<<(NROI * NREG + 255) / 256, 256>>>(rois);
    int ninit4 = FB * NROI * 14 * 128;            // uint4 count for regions 0..13
    init_out14_kernel<<<(ninit4 + 255) / 256, 256>>>((unsigned int*)out);
    roi_pool_band<<<FB * NROI * NTASK, 128>>>(fm, out);
    pool1_fold_kernel<<<(FB * NROI * C4 + 127) / 128, 128>>>(out);
}